// round 4
// baseline (speedup 1.0000x reference)
#include <cuda_runtime.h>
#include <math.h>

#define CC 12
#define BB 64
#define HH 256
#define WW 256
#define NPLANE (HH*WW)
#define NPCLL ((long long)BB*NPLANE)   /* 4194304 values per channel */
#define NBINS 1000
#define FB 8000                        /* fine bins = 8 * NBINS */
#define CAP 6144                       /* gather buffer per (c,q) */

#define F_INF  __int_as_float(0x7f800000)
#define F_NINF __int_as_float(0xff800000)

/* output layout (floats):
   mean[12] var[12] std[12] min[12] max[12] count[1] hist[12000] p02[12] p98[12] */
#define OFF_MEAN  0
#define OFF_VAR   12
#define OFF_STD   24
#define OFF_MIN   36
#define OFF_MAX   48
#define OFF_CNT   60
#define OFF_HIST  61
#define OFF_P02   12061
#define OFF_P98   12073

__device__ double   g_sum[CC];
__device__ double   g_sumsq[CC];
__device__ unsigned g_minenc[CC];
__device__ unsigned g_maxenc[CC];
__device__ unsigned g_fine[CC * FB];
__device__ unsigned g_below[CC];       /* values < 0 (rank offset for quantile) */
__device__ int      g_cnt[CC * 2];
__device__ int      g_lo[CC * 2];
__device__ int      g_hi[CC * 2];
__device__ int      g_r[CC * 2];
__device__ float    g_buf[CC * 2 * CAP];

__device__ __forceinline__ unsigned enc_f(float f) {
    unsigned u = __float_as_uint(f);
    return (u & 0x80000000u) ? ~u : (u | 0x80000000u);
}
__device__ __forceinline__ float dec_f(unsigned u) {
    return __uint_as_float((u & 0x80000000u) ? (u & 0x7FFFFFFFu) : ~u);
}

/* ---------------- K0: reset scratch (graph replays must be idempotent) ---- */
__global__ void kinit() {
    int i = blockIdx.x * blockDim.x + threadIdx.x;
    int stride = gridDim.x * blockDim.x;
    for (int j = i; j < CC * FB; j += stride) g_fine[j] = 0u;
    if (i < CC) {
        g_sum[i] = 0.0; g_sumsq[i] = 0.0;
        g_minenc[i] = 0xFFFFFFFFu; g_maxenc[i] = 0u;
        g_below[i] = 0u;
    }
    if (i < CC * 2) g_cnt[i] = 0;
}

/* ---------------- K1: streaming pass 1 ----------------------------------- */
__global__ void __launch_bounds__(256) pass1(const float* __restrict__ x) {
    __shared__ unsigned s_fine[FB];
    __shared__ double   s_dsum[8], s_dsq[8];
    __shared__ float    s_min[8], s_max[8];
    __shared__ unsigned s_bel[8];

    const int c = blockIdx.y;
    const int b = blockIdx.x;
    for (int j = threadIdx.x; j < FB; j += blockDim.x) s_fine[j] = 0u;
    __syncthreads();

    const float4* p = (const float4*)(x + ((size_t)b * CC + c) * NPLANE);

    double lsum = 0.0, lsq = 0.0;
    float lmin = F_INF, lmax = F_NINF;
    unsigned below = 0;

    const int nvec = NPLANE / 4;
    #pragma unroll 4
    for (int i = threadIdx.x; i < nvec; i += blockDim.x) {
        float4 v = p[i];
        float vals[4] = {v.x, v.y, v.z, v.w};
        #pragma unroll
        for (int t = 0; t < 4; t++) {
            float val = vals[t];
            lsum += (double)val;
            lsq  += (double)val * (double)val;
            lmin = fminf(lmin, val);
            lmax = fmaxf(lmax, val);
            if (val >= 0.0f && val <= 100.0f) {
                int idx = (int)floorf(val * 80.0f);   /* 80 = 8*10, exact wrt *10 */
                idx = min(idx, FB - 1);
                atomicAdd(&s_fine[idx], 1u);
            } else if (val < 0.0f) {
                below++;
            }
        }
    }
    __syncthreads();

    /* merge fine histogram to global */
    for (int j = threadIdx.x; j < FB; j += blockDim.x) {
        unsigned v = s_fine[j];
        if (v) atomicAdd(&g_fine[c * FB + j], v);
    }

    /* block reduce moments/min/max */
    for (int off = 16; off; off >>= 1) {
        lsum += __shfl_down_sync(0xFFFFFFFFu, lsum, off);
        lsq  += __shfl_down_sync(0xFFFFFFFFu, lsq,  off);
        lmin = fminf(lmin, __shfl_down_sync(0xFFFFFFFFu, lmin, off));
        lmax = fmaxf(lmax, __shfl_down_sync(0xFFFFFFFFu, lmax, off));
        below += __shfl_down_sync(0xFFFFFFFFu, below, off);
    }
    int wid = threadIdx.x >> 5, lid = threadIdx.x & 31;
    if (lid == 0) { s_dsum[wid]=lsum; s_dsq[wid]=lsq; s_min[wid]=lmin; s_max[wid]=lmax; s_bel[wid]=below; }
    __syncthreads();
    if (wid == 0) {
        lsum = (lid < 8) ? s_dsum[lid] : 0.0;
        lsq  = (lid < 8) ? s_dsq[lid]  : 0.0;
        lmin = (lid < 8) ? s_min[lid]  : F_INF;
        lmax = (lid < 8) ? s_max[lid]  : F_NINF;
        below= (lid < 8) ? s_bel[lid]  : 0u;
        for (int off = 4; off; off >>= 1) {
            lsum += __shfl_down_sync(0xFFFFFFFFu, lsum, off);
            lsq  += __shfl_down_sync(0xFFFFFFFFu, lsq,  off);
            lmin = fminf(lmin, __shfl_down_sync(0xFFFFFFFFu, lmin, off));
            lmax = fmaxf(lmax, __shfl_down_sync(0xFFFFFFFFu, lmax, off));
            below += __shfl_down_sync(0xFFFFFFFFu, below, off);
        }
        if (lid == 0) {
            atomicAdd(&g_sum[c], lsum);
            atomicAdd(&g_sumsq[c], lsq);
            atomicMin(&g_minenc[c], enc_f(lmin));
            atomicMax(&g_maxenc[c], enc_f(lmax));
            if (below) atomicAdd(&g_below[c], below);
        }
    }
}

/* ---------------- K2: per-channel stats, coarse hist, quantile windows ---- */
__global__ void __launch_bounds__(256) kstats(
    const float* __restrict__ mean_in, const float* __restrict__ var_in,
    const float* __restrict__ count_in, const float* __restrict__ minv_in,
    const float* __restrict__ maxv_in, const float* __restrict__ hist_in,
    float* __restrict__ out)
{
    const int c = blockIdx.x;
    __shared__ int s_bin[4], s_cum[4];

    const unsigned below = g_below[c];

    if (threadIdx.x < 32) {
        const int lane = threadIdx.x;
        const unsigned* fh = g_fine + c * FB;
        const int chunk = FB / 32;            /* 250 */
        const int base = lane * chunk;
        unsigned csum = 0;
        for (int j = 0; j < chunk; j++) csum += fh[base + j];
        unsigned v = csum;
        for (int off = 1; off < 32; off <<= 1) {
            unsigned t = __shfl_up_sync(0xFFFFFFFFu, v, off);
            if (lane >= off) v += t;
        }
        const unsigned excl = v - csum;
        for (int t = 0; t < 4; t++) {
            const int q = t >> 1;
            double p = (q ? 0.98 : 0.02) * (double)(NPCLL - 1);
            long long kk = (long long)floor(p) + (t & 1);
            long long tgt = kk - (long long)below;
            if (tgt >= (long long)excl && tgt < (long long)(excl + csum)) {
                long long acc = excl;
                for (int j = 0; j < chunk; j++) {
                    unsigned cb = fh[base + j];
                    if (tgt < acc + cb) { s_bin[t] = base + j; s_cum[t] = (int)acc; break; }
                    acc += cb;
                }
            }
        }
    }
    __syncthreads();

    if (threadIdx.x == 0) {
        for (int q = 0; q < 2; q++) {
            double p = (q ? 0.98 : 0.02) * (double)(NPCLL - 1);
            long long kk = (long long)floor(p);
            long long tgt = kk - (long long)below;
            g_lo[c * 2 + q] = s_bin[2 * q];
            g_hi[c * 2 + q] = s_bin[2 * q + 1];
            g_r [c * 2 + q] = (int)(tgt - (long long)s_cum[2 * q]);
        }
        /* moments merge */
        const double N  = (double)NPCLL;
        const double bs = g_sum[c], bq = g_sumsq[c];
        const double bm = bs / N;
        const double bv = (bq - bs * bs / N) / (N - 1.0);
        const double bc = (double)BB;
        const double ci = (double)count_in[0];
        const double nab = ci + bc;
        const double mi = (double)mean_in[c], vi = (double)var_in[c];
        const double delta = bm - mi;
        const double nm = (mi * ci + bm * bc) / nab;
        const double nv = (vi * ci + bv * bc + delta * delta * ci * bc / nab) / nab;
        out[OFF_MEAN + c] = (float)nm;
        out[OFF_VAR  + c] = (float)nv;
        out[OFF_STD  + c] = (float)sqrt(nv + 1e-8);
        out[OFF_MIN  + c] = fminf(minv_in[c], dec_f(g_minenc[c]));
        out[OFF_MAX  + c] = fmaxf(maxv_in[c], dec_f(g_maxenc[c]));
        if (c == 0) out[OFF_CNT] = count_in[0] + (float)BB;
    }

    /* coarse 1000-bin hist = 8 fine bins each (bit-exact equivalence) */
    for (int j = threadIdx.x; j < NBINS; j += blockDim.x) {
        const unsigned* fh = g_fine + c * FB + j * 8;
        unsigned s = 0;
        #pragma unroll
        for (int t = 0; t < 8; t++) s += fh[t];
        out[OFF_HIST + c * NBINS + j] = hist_in[c * NBINS + j] + (float)s;
    }
}

/* ---------------- K3: streaming pass 2, gather quantile candidates -------- */
__global__ void __launch_bounds__(256) pass2(const float* __restrict__ x) {
    const int c = blockIdx.y;
    const int b = blockIdx.x;
    const int lo0 = g_lo[c * 2 + 0], hi0 = g_hi[c * 2 + 0];
    const int lo1 = g_lo[c * 2 + 1], hi1 = g_hi[c * 2 + 1];

    const float4* p = (const float4*)(x + ((size_t)b * CC + c) * NPLANE);
    const int nvec = NPLANE / 4;
    #pragma unroll 4
    for (int i = threadIdx.x; i < nvec; i += blockDim.x) {
        float4 v = p[i];
        float vals[4] = {v.x, v.y, v.z, v.w};
        #pragma unroll
        for (int t = 0; t < 4; t++) {
            float val = vals[t];
            if (val >= 0.0f && val <= 100.0f) {
                int idx = (int)floorf(val * 80.0f);
                idx = min(idx, FB - 1);
                if (idx >= lo0 && idx <= hi0) {
                    int pos = atomicAdd(&g_cnt[c * 2 + 0], 1);
                    if (pos < CAP) g_buf[(c * 2 + 0) * CAP + pos] = val;
                }
                if (idx >= lo1 && idx <= hi1) {
                    int pos = atomicAdd(&g_cnt[c * 2 + 1], 1);
                    if (pos < CAP) g_buf[(c * 2 + 1) * CAP + pos] = val;
                }
            }
        }
    }
}

/* ---------------- K4: exact order statistic + interpolation --------------- */
__global__ void __launch_bounds__(256) kselect(float* __restrict__ out) {
    const int c = blockIdx.x >> 1, q = blockIdx.x & 1;
    __shared__ float s[CAP];
    __shared__ float vv[2];
    int n = g_cnt[c * 2 + q];
    if (n > CAP) n = CAP;
    for (int i = threadIdx.x; i < n; i += blockDim.x)
        s[i] = g_buf[(c * 2 + q) * CAP + i];
    if (threadIdx.x == 0) { vv[0] = 0.0f; vv[1] = 0.0f; }
    __syncthreads();

    const int r = g_r[c * 2 + q];
    for (int i = threadIdx.x; i < n; i += blockDim.x) {
        float a = s[i];
        int rk = 0;
        for (int j = 0; j < n; j++) {
            float bsv = s[j];
            rk += (bsv < a) || (bsv == a && j < i);   /* stable rank */
        }
        if (rk == r)     vv[0] = a;
        if (rk == r + 1) vv[1] = a;
    }
    __syncthreads();
    if (threadIdx.x == 0) {
        double p = (q ? 0.98 : 0.02) * (double)(NPCLL - 1);
        double frac = p - floor(p);
        double res = (double)vv[0] + frac * ((double)vv[1] - (double)vv[0]);
        out[(q ? OFF_P98 : OFF_P02) + c] = (float)res;
    }
}

extern "C" void kernel_launch(void* const* d_in, const int* in_sizes, int n_in,
                              void* d_out, int out_size) {
    const float* x       = (const float*)d_in[0];
    const float* mean_in = (const float*)d_in[1];
    const float* var_in  = (const float*)d_in[2];
    const float* cnt_in  = (const float*)d_in[3];
    const float* min_in  = (const float*)d_in[4];
    const float* max_in  = (const float*)d_in[5];
    const float* hist_in = (const float*)d_in[6];
    float* out = (float*)d_out;

    kinit<<<375, 256>>>();
    pass1<<<dim3(BB, CC), 256>>>(x);
    kstats<<<CC, 256>>>(mean_in, var_in, cnt_in, min_in, max_in, hist_in, out);
    pass2<<<dim3(BB, CC), 256>>>(x);
    kselect<<<CC * 2, 256>>>(out);
}

// round 7
// speedup vs baseline: 1.1013x; 1.1013x over previous
#include <cuda_runtime.h>
#include <math.h>

#define CC 12
#define BB 64
#define HH 256
#define WW 256
#define NPLANE (HH*WW)
#define NPCLL ((long long)BB*NPLANE)   /* 4194304 values per channel */
#define NBINS 1000
#define FB 8000                        /* fine bins = 8 * NBINS */
#define CAP 6144                       /* gather buffer per (c,q) */

#define F_INF  __int_as_float(0x7f800000)
#define F_NINF __int_as_float(0xff800000)

/* output layout (floats):
   mean[12] var[12] std[12] min[12] max[12] count[1] hist[12000] p02[12] p98[12] */
#define OFF_MEAN  0
#define OFF_VAR   12
#define OFF_STD   24
#define OFF_MIN   36
#define OFF_MAX   48
#define OFF_CNT   60
#define OFF_HIST  61
#define OFF_P02   12061
#define OFF_P98   12073

__device__ double   g_sum[CC];
__device__ double   g_sumsq[CC];
__device__ unsigned g_minenc[CC];
__device__ unsigned g_maxenc[CC];
__device__ unsigned g_fine[CC * FB];
__device__ unsigned g_below[CC];       /* values < 0 (rank offset for quantile) */
__device__ int      g_cnt[CC * 2];
__device__ float    g_blo[CC * 2];     /* float window bounds on v*80 */
__device__ float    g_bhi[CC * 2];
__device__ int      g_r[CC * 2];
__device__ float    g_buf[CC * 2 * CAP];

__device__ __forceinline__ unsigned enc_f(float f) {
    unsigned u = __float_as_uint(f);
    return (u & 0x80000000u) ? ~u : (u | 0x80000000u);
}
__device__ __forceinline__ float dec_f(unsigned u) {
    return __uint_as_float((u & 0x80000000u) ? (u & 0x7FFFFFFFu) : ~u);
}

/* ---------------- K0: reset scratch (graph replays must be idempotent) ---- */
__global__ void kinit() {
    int i = blockIdx.x * blockDim.x + threadIdx.x;
    int stride = gridDim.x * blockDim.x;
    for (int j = i; j < CC * FB; j += stride) g_fine[j] = 0u;
    if (i < CC) {
        g_sum[i] = 0.0; g_sumsq[i] = 0.0;
        g_minenc[i] = 0xFFFFFFFFu; g_maxenc[i] = 0u;
        g_below[i] = 0u;
    }
    if (i < CC * 2) g_cnt[i] = 0;
}

/* ---------------- K1: streaming pass 1 ----------------------------------- */
/* grid (BB, CC), 256 threads. 16384 vec4 per block, 64 iters/thread in
   4 tiles of 16. fp32 partial sums inside a tile, folded to f64 per tile. */
__global__ void __launch_bounds__(256) pass1(const float* __restrict__ x) {
    __shared__ unsigned s_fine[FB];
    __shared__ double   s_dsum[8], s_dsq[8];
    __shared__ float    s_min[8], s_max[8];
    __shared__ unsigned s_bel[8];

    const int c = blockIdx.y;
    const int b = blockIdx.x;
    for (int j = threadIdx.x; j < FB; j += blockDim.x) s_fine[j] = 0u;
    __syncthreads();

    const float4* p = (const float4*)(x + ((size_t)b * CC + c) * NPLANE);

    double dsum = 0.0, dsq = 0.0;
    float lmin = F_INF, lmax = F_NINF;
    unsigned below = 0;

    int i = threadIdx.x;
    #pragma unroll 1
    for (int outer = 0; outer < 4; outer++) {
        float a0 = 0.f, a1 = 0.f, a2 = 0.f, a3 = 0.f;
        float q0 = 0.f, q1 = 0.f, q2 = 0.f, q3 = 0.f;
        #pragma unroll
        for (int inner = 0; inner < 16; inner++) {
            float4 v = p[i]; i += 256;
            a0 += v.x; q0 = fmaf(v.x, v.x, q0);
            a1 += v.y; q1 = fmaf(v.y, v.y, q1);
            a2 += v.z; q2 = fmaf(v.z, v.z, q2);
            a3 += v.w; q3 = fmaf(v.w, v.w, q3);
            lmin = fminf(fminf(lmin, fminf(v.x, v.y)), fminf(v.z, v.w));
            lmax = fmaxf(fmaxf(lmax, fmaxf(v.x, v.y)), fmaxf(v.z, v.w));
            float vals[4] = {v.x, v.y, v.z, v.w};
            #pragma unroll
            for (int t = 0; t < 4; t++) {
                float val = vals[t];
                if (val >= 0.0f && val <= 100.0f) {
                    int idx = (int)floorf(val * 80.0f);   /* 80=8*10, exact wrt *10 */
                    idx = min(idx, FB - 1);
                    atomicAdd(&s_fine[idx], 1u);
                } else if (val < 0.0f) {
                    below++;
                }
            }
        }
        dsum += (double)((a0 + a1) + (a2 + a3));
        dsq  += (double)((q0 + q1) + (q2 + q3));
    }
    __syncthreads();

    /* merge fine histogram to global */
    for (int j = threadIdx.x; j < FB; j += blockDim.x) {
        unsigned v = s_fine[j];
        if (v) atomicAdd(&g_fine[c * FB + j], v);
    }

    /* block reduce moments/min/max */
    for (int off = 16; off; off >>= 1) {
        dsum += __shfl_down_sync(0xFFFFFFFFu, dsum, off);
        dsq  += __shfl_down_sync(0xFFFFFFFFu, dsq,  off);
        lmin = fminf(lmin, __shfl_down_sync(0xFFFFFFFFu, lmin, off));
        lmax = fmaxf(lmax, __shfl_down_sync(0xFFFFFFFFu, lmax, off));
        below += __shfl_down_sync(0xFFFFFFFFu, below, off);
    }
    int wid = threadIdx.x >> 5, lid = threadIdx.x & 31;
    if (lid == 0) { s_dsum[wid]=dsum; s_dsq[wid]=dsq; s_min[wid]=lmin; s_max[wid]=lmax; s_bel[wid]=below; }
    __syncthreads();
    if (wid == 0) {
        dsum = (lid < 8) ? s_dsum[lid] : 0.0;
        dsq  = (lid < 8) ? s_dsq[lid]  : 0.0;
        lmin = (lid < 8) ? s_min[lid]  : F_INF;
        lmax = (lid < 8) ? s_max[lid]  : F_NINF;
        below= (lid < 8) ? s_bel[lid]  : 0u;
        for (int off = 4; off; off >>= 1) {
            dsum += __shfl_down_sync(0xFFFFFFFFu, dsum, off);
            dsq  += __shfl_down_sync(0xFFFFFFFFu, dsq,  off);
            lmin = fminf(lmin, __shfl_down_sync(0xFFFFFFFFu, lmin, off));
            lmax = fmaxf(lmax, __shfl_down_sync(0xFFFFFFFFu, lmax, off));
            below += __shfl_down_sync(0xFFFFFFFFu, below, off);
        }
        if (lid == 0) {
            atomicAdd(&g_sum[c], dsum);
            atomicAdd(&g_sumsq[c], dsq);
            atomicMin(&g_minenc[c], enc_f(lmin));
            atomicMax(&g_maxenc[c], enc_f(lmax));
            if (below) atomicAdd(&g_below[c], below);
        }
    }
}

/* ---------------- K2: per-channel stats, coarse hist, quantile windows ---- */
__global__ void __launch_bounds__(256) kstats(
    const float* __restrict__ mean_in, const float* __restrict__ var_in,
    const float* __restrict__ count_in, const float* __restrict__ minv_in,
    const float* __restrict__ maxv_in, const float* __restrict__ hist_in,
    float* __restrict__ out)
{
    const int c = blockIdx.x;
    __shared__ int s_bin[4], s_cum[4];

    const unsigned below = g_below[c];

    if (threadIdx.x < 32) {
        const int lane = threadIdx.x;
        const unsigned* fh = g_fine + c * FB;
        const int chunk = FB / 32;            /* 250 */
        const int base = lane * chunk;
        unsigned csum = 0;
        for (int j = 0; j < chunk; j++) csum += fh[base + j];
        unsigned v = csum;
        for (int off = 1; off < 32; off <<= 1) {
            unsigned t = __shfl_up_sync(0xFFFFFFFFu, v, off);
            if (lane >= off) v += t;
        }
        const unsigned excl = v - csum;
        for (int t = 0; t < 4; t++) {
            const int q = t >> 1;
            double p = (q ? 0.98 : 0.02) * (double)(NPCLL - 1);
            long long kk = (long long)floor(p) + (t & 1);
            long long tgt = kk - (long long)below;
            if (tgt >= (long long)excl && tgt < (long long)(excl + csum)) {
                long long acc = excl;
                for (int j = 0; j < chunk; j++) {
                    unsigned cb = fh[base + j];
                    if (tgt < acc + cb) { s_bin[t] = base + j; s_cum[t] = (int)acc; break; }
                    acc += cb;
                }
            }
        }
    }
    __syncthreads();

    if (threadIdx.x == 0) {
        for (int q = 0; q < 2; q++) {
            double p = (q ? 0.98 : 0.02) * (double)(NPCLL - 1);
            long long kk = (long long)floor(p);
            long long tgt = kk - (long long)below;
            g_blo[c * 2 + q] = (float)s_bin[2 * q];          /* v80 >= lo      */
            g_bhi[c * 2 + q] = (float)(s_bin[2 * q + 1] + 1);/* v80c < hi + 1  */
            g_r  [c * 2 + q] = (int)(tgt - (long long)s_cum[2 * q]);
        }
        /* moments merge */
        const double N  = (double)NPCLL;
        const double bs = g_sum[c], bq = g_sumsq[c];
        const double bm = bs / N;
        const double bv = (bq - bs * bs / N) / (N - 1.0);
        const double bc = (double)BB;
        const double ci = (double)count_in[0];
        const double nab = ci + bc;
        const double mi = (double)mean_in[c], vi = (double)var_in[c];
        const double delta = bm - mi;
        const double nm = (mi * ci + bm * bc) / nab;
        const double nv = (vi * ci + bv * bc + delta * delta * ci * bc / nab) / nab;
        out[OFF_MEAN + c] = (float)nm;
        out[OFF_VAR  + c] = (float)nv;
        out[OFF_STD  + c] = (float)sqrt(nv + 1e-8);
        out[OFF_MIN  + c] = fminf(minv_in[c], dec_f(g_minenc[c]));
        out[OFF_MAX  + c] = fmaxf(maxv_in[c], dec_f(g_maxenc[c]));
        if (c == 0) out[OFF_CNT] = count_in[0] + (float)BB;
    }

    /* coarse 1000-bin hist = 8 fine bins each (bit-exact equivalence) */
    for (int j = threadIdx.x; j < NBINS; j += blockDim.x) {
        const unsigned* fh = g_fine + c * FB + j * 8;
        unsigned s = 0;
        #pragma unroll
        for (int t = 0; t < 8; t++) s += fh[t];
        out[OFF_HIST + c * NBINS + j] = hist_in[c * NBINS + j] + (float)s;
    }
}

/* ---------------- K3: streaming pass 2, gather quantile candidates -------- */
/* grid (BB*2, CC): each block handles half a plane (8192 vec4, 32/thread).
   Candidate test on v80 with float bounds; fminf clamp makes val==100 land
   in bin 7999 exactly as pass1's clamped floor did. */
__global__ void __launch_bounds__(256) pass2(const float* __restrict__ x) {
    const int c = blockIdx.y;
    const int b = blockIdx.x >> 1;
    const int half = blockIdx.x & 1;
    const float lo0 = g_blo[c * 2 + 0], hi0 = g_bhi[c * 2 + 0];
    const float lo1 = g_blo[c * 2 + 1], hi1 = g_bhi[c * 2 + 1];

    const float4* p = (const float4*)(x + ((size_t)b * CC + c) * NPLANE)
                      + half * (NPLANE / 8);
    const int nvec = NPLANE / 8;              /* 8192 */
    #pragma unroll 8
    for (int i = threadIdx.x; i < nvec; i += 256) {
        float4 v = p[i];
        float vals[4] = {v.x, v.y, v.z, v.w};
        #pragma unroll
        for (int t = 0; t < 4; t++) {
            float val = vals[t];
            if (val <= 100.0f) {
                float v80 = fminf(val * 80.0f, 7999.5f);
                if (v80 >= lo0 && v80 < hi0) {
                    int pos = atomicAdd(&g_cnt[c * 2 + 0], 1);
                    if (pos < CAP) g_buf[(c * 2 + 0) * CAP + pos] = val;
                }
                if (v80 >= lo1 && v80 < hi1) {
                    int pos = atomicAdd(&g_cnt[c * 2 + 1], 1);
                    if (pos < CAP) g_buf[(c * 2 + 1) * CAP + pos] = val;
                }
            }
        }
    }
}

/* ---------------- K4: exact order statistic + interpolation --------------- */
__global__ void __launch_bounds__(256) kselect(float* __restrict__ out) {
    const int c = blockIdx.x >> 1, q = blockIdx.x & 1;
    __shared__ float s[CAP];
    __shared__ float vv[2];
    int n = g_cnt[c * 2 + q];
    if (n > CAP) n = CAP;
    for (int i = threadIdx.x; i < n; i += blockDim.x)
        s[i] = g_buf[(c * 2 + q) * CAP + i];
    if (threadIdx.x == 0) { vv[0] = 0.0f; vv[1] = 0.0f; }
    __syncthreads();

    const int r = g_r[c * 2 + q];
    for (int i = threadIdx.x; i < n; i += blockDim.x) {
        float a = s[i];
        int rk = 0;
        for (int j = 0; j < n; j++) {
            float bsv = s[j];
            rk += (bsv < a) || (bsv == a && j < i);   /* stable rank */
        }
        if (rk == r)     vv[0] = a;
        if (rk == r + 1) vv[1] = a;
    }
    __syncthreads();
    if (threadIdx.x == 0) {
        double p = (q ? 0.98 : 0.02) * (double)(NPCLL - 1);
        double frac = p - floor(p);
        double res = (double)vv[0] + frac * ((double)vv[1] - (double)vv[0]);
        out[(q ? OFF_P98 : OFF_P02) + c] = (float)res;
    }
}

extern "C" void kernel_launch(void* const* d_in, const int* in_sizes, int n_in,
                              void* d_out, int out_size) {
    const float* x       = (const float*)d_in[0];
    const float* mean_in = (const float*)d_in[1];
    const float* var_in  = (const float*)d_in[2];
    const float* cnt_in  = (const float*)d_in[3];
    const float* min_in  = (const float*)d_in[4];
    const float* max_in  = (const float*)d_in[5];
    const float* hist_in = (const float*)d_in[6];
    float* out = (float*)d_out;

    kinit<<<375, 256>>>();
    pass1<<<dim3(BB, CC), 256>>>(x);
    kstats<<<CC, 256>>>(mean_in, var_in, cnt_in, min_in, max_in, hist_in, out);
    pass2<<<dim3(BB * 2, CC), 256>>>(x);
    kselect<<<CC * 2, 256>>>(out);
}